// round 2
// baseline (speedup 1.0000x reference)
#include <cuda_runtime.h>
#include <cuda_bf16.h>
#include <math.h>

// Problem constants (fixed by setup_inputs)
constexpr int B_ = 64;
constexpr int K_ = 8400;
constexpr int C_ = 15;
constexpr int N_ = B_ * K_;          // 537600 slots
constexpr float IMGF = 640.0f;
constexpr float ALPHA_ = 0.25f;

constexpr int NBLOCKS = 1184;        // 8 * 148 SMs
constexpr int NTHREADS = 256;

// Per-block partial sums: [cls, reg, ang, iou, obj, fg_count], padded to 8
__device__ float g_part[NBLOCKS][8];

__device__ __forceinline__ float sl1(float x) {
    float d = fabsf(x);
    return (d < 1.0f) ? 0.5f * d * d : d - 0.5f;
}

__device__ __forceinline__ float warp_sum(float v) {
    #pragma unroll
    for (int o = 16; o > 0; o >>= 1) v += __shfl_down_sync(0xffffffffu, v, o);
    return v;
}

__global__ __launch_bounds__(NTHREADS) void otdet_reduce(
    const float* __restrict__ centers,   // [N,2]
    const float* __restrict__ wh,        // [N,2]
    const float* __restrict__ angles,    // [N,1]
    const float* __restrict__ logits,    // [N,C]
    const float* __restrict__ conf,      // [N,1]
    const float* __restrict__ targets,   // [N,5]
    const int*   __restrict__ labels)    // [N]
{
    float s_cls = 0.f, s_reg = 0.f, s_ang = 0.f, s_iou = 0.f, s_obj = 0.f, s_fg = 0.f;
    const float invs = 1.0f / IMGF;

    for (int i = blockIdx.x * NTHREADS + threadIdx.x; i < N_; i += NBLOCKS * NTHREADS) {
        int lab = labels[i];
        bool fg = (lab >= 0);

        // ---- focal classification loss over C classes ----
        #pragma unroll
        for (int c = 0; c < C_; c++) {
            float l  = logits[i * C_ + c];
            bool  oh = (c == lab);
            float e    = __expf(-fabsf(l));          // exp(-|l|)
            float soft = __logf(1.0f + e);           // log1p(exp(-|l|))
            float bce  = fmaxf(l, 0.0f) - (oh ? l : 0.0f) + soft;
            float inv  = __fdividef(1.0f, 1.0f + e);
            float p    = (l >= 0.0f) ? inv : e * inv;  // sigmoid(l)
            float ompt = oh ? (1.0f - p) : p;          // (1 - p_t)
            float a_t  = oh ? ALPHA_ : (1.0f - ALPHA_);
            s_cls += a_t * ompt * ompt * bce;
        }

        // ---- objectness BCE ----
        float cf    = conf[i];
        float logc  = fmaxf(__logf(cf), -100.0f);
        float log1c = fmaxf(__logf(1.0f - cf), -100.0f);
        s_obj -= fg ? logc : log1c;

        if (fg) {
            s_fg += 1.0f;
            float cx = centers[2 * i],     cy = centers[2 * i + 1];
            float w  = wh[2 * i],          h  = wh[2 * i + 1];
            float gx = targets[5 * i],     gy = targets[5 * i + 1];
            float gw = targets[5 * i + 2], gh = targets[5 * i + 3];
            float ga = targets[5 * i + 4];

            // smooth-L1 box regression (normalized)
            s_reg += sl1((cx - gx) * invs) + sl1((cy - gy) * invs)
                   + sl1((w  - gw) * invs) + sl1((h  - gh) * invs);

            // angle loss on doubled angle
            float pa2 = 2.0f * angles[i];
            float ga2 = 2.0f * ga;
            float sp, cp, sg, cg;
            __sincosf(pa2, &sp, &cp);
            __sincosf(ga2, &sg, &cg);
            s_ang += sl1(sp - sg) + sl1(cp - cg);

            // aligned (axis-parallel) IoU
            float iw = fminf(cx + 0.5f * w, gx + 0.5f * gw) - fmaxf(cx - 0.5f * w, gx - 0.5f * gw);
            float ih = fminf(cy + 0.5f * h, gy + 0.5f * gh) - fmaxf(cy - 0.5f * h, gy - 0.5f * gh);
            float inter = fmaxf(iw, 0.0f) * fmaxf(ih, 0.0f);
            float ap = w * h, ag = gw * gh;
            float iou = __fdividef(inter, ap + ag - inter + 1e-7f);
            s_iou += 1.0f - iou;
        }
    }

    // ---- block reduction ----
    __shared__ float sm[NTHREADS / 32][6];
    float vals[6] = {s_cls, s_reg, s_ang, s_iou, s_obj, s_fg};
    int lane = threadIdx.x & 31;
    int wid  = threadIdx.x >> 5;
    #pragma unroll
    for (int j = 0; j < 6; j++) {
        float v = warp_sum(vals[j]);
        if (lane == 0) sm[wid][j] = v;
    }
    __syncthreads();
    if (wid == 0) {
        #pragma unroll
        for (int j = 0; j < 6; j++) {
            float v = (lane < NTHREADS / 32) ? sm[lane][j] : 0.0f;
            v = warp_sum(v);
            if (lane == 0) g_part[blockIdx.x][j] = v;
        }
    }
}

__global__ void otdet_finalize(float* __restrict__ out) {
    __shared__ double sm[NTHREADS / 32][6];
    double acc[6] = {0, 0, 0, 0, 0, 0};
    for (int b = threadIdx.x; b < NBLOCKS; b += NTHREADS) {
        #pragma unroll
        for (int j = 0; j < 6; j++) acc[j] += (double)g_part[b][j];
    }
    int lane = threadIdx.x & 31;
    int wid  = threadIdx.x >> 5;
    #pragma unroll
    for (int j = 0; j < 6; j++) {
        double v = acc[j];
        #pragma unroll
        for (int o = 16; o > 0; o >>= 1) v += __shfl_down_sync(0xffffffffu, v, o);
        if (lane == 0) sm[wid][j] = v;
    }
    __syncthreads();
    if (threadIdx.x == 0) {
        double t[6];
        #pragma unroll
        for (int j = 0; j < 6; j++) {
            double v = 0;
            for (int w = 0; w < NTHREADS / 32; w++) v += sm[w][j];
            t[j] = v;
        }
        double n_fg = t[5] > 1.0 ? t[5] : 1.0;
        double total = (t[0] + 5.0 * t[1] + 1.0 * t[2] + 2.0 * t[3]) / n_fg
                     + t[4] / (double)(B_ * K_);
        out[0] = (float)total;
    }
}

extern "C" void kernel_launch(void* const* d_in, const int* in_sizes, int n_in,
                              void* d_out, int out_size) {
    // metadata order: centers, wh, angles, cls_logits, conf,
    //                 slot_targets, slot_labels, fg_mask, img_size
    const float* centers = (const float*)d_in[0];
    const float* wh      = (const float*)d_in[1];
    const float* angles  = (const float*)d_in[2];
    const float* logits  = (const float*)d_in[3];
    const float* conf    = (const float*)d_in[4];
    const float* targets = (const float*)d_in[5];
    const int*   labels  = (const int*)d_in[6];
    float* out = (float*)d_out;

    otdet_reduce<<<NBLOCKS, NTHREADS>>>(centers, wh, angles, logits, conf, targets, labels);
    otdet_finalize<<<1, NTHREADS>>>(out);
}